// round 3
// baseline (speedup 1.0000x reference)
#include <cuda_runtime.h>
#include <cuda_bf16.h>
#include <math_constants.h>
#include <stdint.h>

// Problem shape (fixed by the dataset)
constexpr int B       = 4;
constexpr int N       = 32768;
constexpr int NQ      = 2048;
constexpr int K       = 16;
constexpr int QSTRIDE = N / NQ;   // 16

constexpr int TILE = 8192;            // candidate points per smem tile
constexpr int WPB  = 8;               // warps (queries) per block
constexpr int THREADS = WPB * 32;     // 256
constexpr int SMEM_BYTES = TILE * 3 * sizeof(float);  // 96 KB

// One warp per query. Each lane scans an interleaved 1/32 partition of the
// candidate set keeping a sorted top-K in registers, then the warp merges
// 32 sorted lists with an exact (d, idx)-lexicographic arg-min, matching
// jax.lax.top_k ordering (ascending distance, ties -> smaller index).
__global__ __launch_bounds__(THREADS, 2)
void knn_kernel(const float* __restrict__ xyz,
                float* __restrict__ out) {   // [idx: B*NQ*K][pts: B*NQ*3], all fp32
    extern __shared__ float s[];   // TILE*3 floats, raw float3 layout

    const int lane = threadIdx.x & 31;
    const int warp = threadIdx.x >> 5;
    const int qg   = blockIdx.x * WPB + warp;     // global query id, 0..B*NQ-1
    const int b    = qg >> 11;                    // / NQ (NQ = 2048)
    const int q    = qg & (NQ - 1);

    const float* __restrict__ base = xyz + (size_t)b * N * 3;
    const int qidx = q * QSTRIDE;

    const float qx = base[qidx * 3 + 0];
    const float qy = base[qidx * 3 + 1];
    const float qz = base[qidx * 3 + 2];

    // Per-lane sorted top-K (ascending distance)
    float bd[K];
    int   bi[K];
#pragma unroll
    for (int k = 0; k < K; ++k) { bd[k] = CUDART_INF_F; bi[k] = 0x7fffffff; }

    for (int t = 0; t < N; t += TILE) {
        __syncthreads();
        // Cooperative tile load: TILE*3 contiguous floats, vectorized
        {
            const float4* __restrict__ g = (const float4*)(base + (size_t)t * 3);
            float4* sm4 = (float4*)s;
#pragma unroll
            for (int k = threadIdx.x; k < (TILE * 3) / 4; k += THREADS)
                sm4[k] = g[k];
        }
        __syncthreads();

        // Lane-interleaved scan: word index 3*(j*32+lane)+c -> banks
        // (3*lane + c) mod 32, conflict-free (gcd(3,32)=1).
        const float* __restrict__ sp = s + 3 * lane;
#pragma unroll 4
        for (int j = 0; j < TILE / 32; ++j) {
            const float px = sp[96 * j + 0];
            const float py = sp[96 * j + 1];
            const float pz = sp[96 * j + 2];
            // Bit-exact with reference fp32: no FMA contraction,
            // association ((dx^2 + dy^2) + dz^2).
            const float dx = __fsub_rn(qx, px);
            const float dy = __fsub_rn(qy, py);
            const float dz = __fsub_rn(qz, pz);
            const float d  = __fadd_rn(__fadd_rn(__fmul_rn(dx, dx),
                                                 __fmul_rn(dy, dy)),
                                       __fmul_rn(dz, dz));
            if (d < bd[K - 1]) {
                // Replace worst and bubble up (strict <, so equal-distance
                // earlier (smaller) indices stay ranked first).
                bd[K - 1] = d;
                bi[K - 1] = t + j * 32 + lane;
#pragma unroll
                for (int k = K - 1; k > 0; --k) {
                    if (bd[k] < bd[k - 1]) {
                        float td = bd[k]; bd[k] = bd[k - 1]; bd[k - 1] = td;
                        int   ti = bi[k]; bi[k] = bi[k - 1]; bi[k - 1] = ti;
                    }
                }
            }
        }
    }

    // Warp merge: 16 rounds of lexicographic (d, idx) arg-min over 32 lane
    // cursors. Keys are unique (disjoint index partitions) so the winner
    // lane is unambiguous.
    int cur = 0;
    int out_i = 0;   // lane r holds winner of round r
#pragma unroll
    for (int r = 0; r < K; ++r) {
        float vd = (cur < K) ? bd[cur] : CUDART_INF_F;
        int   vi = (cur < K) ? bi[cur] : 0x7fffffff;
        int   vl = lane;
#pragma unroll
        for (int off = 16; off > 0; off >>= 1) {
            const float od = __shfl_xor_sync(0xffffffffu, vd, off);
            const int   oi = __shfl_xor_sync(0xffffffffu, vi, off);
            const int   ol = __shfl_xor_sync(0xffffffffu, vl, off);
            if (od < vd || (od == vd && oi < vi)) { vd = od; vi = oi; vl = ol; }
        }
        if (lane == vl) ++cur;        // winner lane consumes its head
        if (lane == r)  out_i = vi;   // round-r winner kept by lane r
    }

    // Output 0: idx, shape (B, NQ, K, 1), written as float32 (values < 2^15,
    // exactly representable). Output 1: pts, shape (B, NQ, 3), float32.
    float* __restrict__ out_idx = out;
    float* __restrict__ out_pts = out + (size_t)B * NQ * K;

    if (lane < K)
        out_idx[(size_t)qg * K + lane] = (float)out_i;
    if (lane == 0) {
        out_pts[(size_t)qg * 3 + 0] = qx;
        out_pts[(size_t)qg * 3 + 1] = qy;
        out_pts[(size_t)qg * 3 + 2] = qz;
    }
}

extern "C" void kernel_launch(void* const* d_in, const int* in_sizes, int n_in,
                              void* d_out, int out_size) {
    (void)in_sizes; (void)n_in; (void)out_size;
    const float* xyz = (const float*)d_in[0];
    float* out = (float*)d_out;

    static bool attr_set = false;
    if (!attr_set) {
        cudaFuncSetAttribute(knn_kernel,
                             cudaFuncAttributeMaxDynamicSharedMemorySize,
                             SMEM_BYTES);
        attr_set = true;
    }

    const int grid = (B * NQ) / WPB;   // 1024 blocks
    knn_kernel<<<grid, THREADS, SMEM_BYTES>>>(xyz, out);
}